// round 10
// baseline (speedup 1.0000x reference)
#include <cuda_runtime.h>
#include <cuda_fp16.h>
#include <math.h>
#include <stdint.h>

#define T 2048
#define H 1024
#define M 512
#define E 32
#define TOPK 4
#define NROWS (T * TOPK)
#define PROWS (NROWS + 128)

// ------------------------- static device scratch ---------------------------
__device__ int      g_count[E];
__device__ int      g_off[E];
__device__ int      g_typre[E + 1];
__device__ int      g_tok[E * T];
__device__ float    g_wt[E * T];
__device__ uint32_t g_hbufw[(size_t)PROWS * M / 2];   // half2 words
__device__ float    g_part[(size_t)NROWS * H];

// ------------------------- helpers -----------------------------------------
__device__ __forceinline__ uint32_t smem_u32(const void* p) {
    return (uint32_t)__cvta_generic_to_shared(p);
}
__device__ __forceinline__ uint32_t f2h2(float a, float b) {
    uint32_t r;
    asm("cvt.rn.f16x2.f32 %0, %1, %2;" : "=r"(r) : "f"(b), "f"(a));
    return r;
}
__device__ __forceinline__ uint4 pack4(float4 a, float4 b) {
    uint4 o;
    o.x = f2h2(a.x, a.y); o.y = f2h2(a.z, a.w);
    o.z = f2h2(b.x, b.y); o.w = f2h2(b.z, b.w);
    return o;
}
__device__ __forceinline__ void ldm4(uint32_t* r, uint32_t addr) {
    asm volatile("ldmatrix.sync.aligned.m8n8.x4.shared.b16 {%0,%1,%2,%3}, [%4];"
        : "=r"(r[0]), "=r"(r[1]), "=r"(r[2]), "=r"(r[3]) : "r"(addr));
}
__device__ __forceinline__ void mma_f16(float* c, const uint32_t* a, uint32_t b0, uint32_t b1) {
    asm volatile("mma.sync.aligned.m16n8k16.row.col.f32.f16.f16.f32 "
        "{%0,%1,%2,%3}, {%4,%5,%6,%7}, {%8,%9}, {%0,%1,%2,%3};"
        : "+f"(c[0]), "+f"(c[1]), "+f"(c[2]), "+f"(c[3])
        : "r"(a[0]), "r"(a[1]), "r"(a[2]), "r"(a[3]), "r"(b0), "r"(b1));
}

// smem row geometry: k32 chunk = 16 half2 words + 4 pad = 20 words = 80 bytes
#define RWORDS 20
#define RBYTES 80

// ------------------------- small kernels -----------------------------------
__global__ void zero_counts() { if (threadIdx.x < E) g_count[threadIdx.x] = 0; }

__global__ void router_kernel(const float* __restrict__ x,
                              const float* __restrict__ gate_w) {
    __shared__ float xs[H];
    __shared__ float logits[E];
    int t = blockIdx.x;
    const float* xr = x + (size_t)t * H;
    for (int i = threadIdx.x; i < H; i += blockDim.x) xs[i] = xr[i];
    __syncthreads();
    int warp = threadIdx.x >> 5, lane = threadIdx.x & 31;
    for (int e = warp; e < E; e += 4) {
        const float* w = gate_w + (size_t)e * H;
        float s = 0.f;
        for (int i = lane; i < H; i += 32) s += xs[i] * w[i];
        #pragma unroll
        for (int o = 16; o > 0; o >>= 1) s += __shfl_xor_sync(0xffffffffu, s, o);
        if (lane == 0) logits[e] = s;
    }
    __syncthreads();
    if (threadIdx.x == 0) {
        int ids[TOPK]; float vals[TOPK];
        unsigned used = 0;
        for (int k = 0; k < TOPK; k++) {
            float best = -INFINITY; int bi = 0;
            for (int e = 0; e < E; e++)
                if (!((used >> e) & 1u) && logits[e] > best) { best = logits[e]; bi = e; }
            used |= (1u << bi); ids[k] = bi; vals[k] = best;
        }
        float mx = vals[0], se = 0.f, w4[TOPK];
        for (int k = 0; k < TOPK; k++) { w4[k] = expf(vals[k] - mx); se += w4[k]; }
        float inv = 1.0f / se;
        for (int k = 0; k < TOPK; k++) {
            int e = ids[k];
            int pos = atomicAdd(&g_count[e], 1);
            g_tok[e * T + pos] = t * TOPK + k;
            g_wt[e * T + pos] = w4[k] * inv;
        }
    }
}

__global__ void scan_kernel() {
    int lane = threadIdx.x;
    int c = g_count[lane];
    int ex = c;
    #pragma unroll
    for (int o = 1; o < 32; o <<= 1) {
        int v = __shfl_up_sync(0xffffffffu, ex, o);
        if (lane >= o) ex += v;
    }
    g_off[lane] = ex - c;
    int ty = (c + 127) >> 7;
    int tp = ty;
    #pragma unroll
    for (int o = 1; o < 32; o <<= 1) {
        int v = __shfl_up_sync(0xffffffffu, tp, o);
        if (lane >= o) tp += v;
    }
    g_typre[lane] = tp - ty;
    if (lane == 31) g_typre[E] = tp;
}

// ------------------------- gate/up fp16 mma GEMM ---------------------------
// persistent; 256 threads, warps 4x2; block 128 rows x 64 m-cols;
// warp tile 32x32 carrying BOTH gate and up; K chunk 32
#define GU_STAGEW 5120
#define GU_SMEMB  (2 * GU_STAGEW * 4)      // 40960 bytes

__global__ void __launch_bounds__(256, 2)
gateup_mma(const float* __restrict__ x,
           const float* __restrict__ wg, const float* __restrict__ wu) {
    extern __shared__ uint32_t sm[];
    __shared__ int   styp[E + 1];
    __shared__ int   said_s[128];
    __shared__ float swt_s[128];

    int tid = threadIdx.x, lane = tid & 31, wid = tid >> 5;
    int gid = lane >> 2, tig = lane & 3;
    int wm = wid & 3, wn = wid >> 2;

    if (tid <= E) styp[tid] = g_typre[tid];
    __syncthreads();
    int totalW = styp[E] * 8;

    uint32_t sbase = smem_u32(sm);
    int a_ro = lane & 15;
    int a_kw = (lane >> 4) * 16;             // bytes
    uint32_t adrA0 = sbase + (uint32_t)(wm * 32 + a_ro) * RBYTES + a_kw;
    uint32_t adrA1 = adrA0 + 16 * RBYTES;
    int b_ro = (lane & 7) + ((lane & 16) >> 1);
    int b_kw = (lane & 8) ? 16 : 0;
    uint32_t adrG0 = sbase + 128 * RBYTES + (uint32_t)(wn * 32 + b_ro) * RBYTES + b_kw;
    uint32_t adrG1 = adrG0 + 16 * RBYTES;
    uint32_t adrU0 = adrG0 + 64 * RBYTES;
    uint32_t adrU1 = adrU0 + 16 * RBYTES;

    int arow = tid >> 1, ah = tid & 1;       // A: 128 rows, 2 halves of k32
    int grow = tid >> 2, gq = tid & 3;       // G/U: 64 rows, 4 quarters

    for (int w = blockIdx.x; w < totalW; w += gridDim.x) {
        int ytl = w >> 3, xt = w & 7;
        int e = 0;
        while (styp[e + 1] <= ytl) e++;
        int t0 = (ytl - styp[e]) * 128;
        int m0 = xt * 64;
        int n  = g_count[e];
        int gbase = g_off[e] + t0;

        __syncthreads();
        if (tid < 128) {
            int slot = t0 + tid;
            bool v = slot < n;
            said_s[tid] = v ? g_tok[e * T + slot] : -1;
            swt_s[tid]  = v ? g_wt[e * T + slot] : 0.f;
        }
        __syncthreads();
        int aid = said_s[arow];

        const float* wgb = wg + ((size_t)e * M + m0) * H;
        const float* wub = wu + ((size_t)e * M + m0) * H;
        const float* ap  = (aid >= 0) ? x + (size_t)(aid >> 2) * H + ah * 16 : nullptr;
        const float* gp0 = wgb + (size_t)grow * H + gq * 8;
        const float* up0 = wub + (size_t)grow * H + gq * 8;

        float accG[2][4][4], accU[2][4][4];
        #pragma unroll
        for (int i = 0; i < 2; i++)
            #pragma unroll
            for (int j = 0; j < 4; j++)
                #pragma unroll
                for (int q = 0; q < 4; q++) { accG[i][j][q] = 0.f; accU[i][j][q] = 0.f; }

        uint4 qa0, qa1, qg, qu;
        auto ldc = [&](int c) {
            int ko = c * 32;
            if (ap) {
                float4 f0 = *(const float4*)(ap + ko);
                float4 f1 = *(const float4*)(ap + ko + 4);
                float4 f2 = *(const float4*)(ap + ko + 8);
                float4 f3 = *(const float4*)(ap + ko + 12);
                qa0 = pack4(f0, f1); qa1 = pack4(f2, f3);
            } else {
                qa0 = make_uint4(0, 0, 0, 0); qa1 = qa0;
            }
            float4 g0 = *(const float4*)(gp0 + ko);
            float4 g1 = *(const float4*)(gp0 + ko + 4);
            qg = pack4(g0, g1);
            float4 u0 = *(const float4*)(up0 + ko);
            float4 u1 = *(const float4*)(up0 + ko + 4);
            qu = pack4(u0, u1);
        };
        auto sts = [&](int s) {
            uint32_t* st = sm + s * GU_STAGEW;
            uint32_t* A = st;
            uint32_t* G = st + 128 * RWORDS;
            uint32_t* U = st + 192 * RWORDS;
            *(uint4*)(A + arow * RWORDS + ah * 8)     = qa0;
            *(uint4*)(A + arow * RWORDS + ah * 8 + 4) = qa1;
            *(uint4*)(G + grow * RWORDS + gq * 4)     = qg;
            *(uint4*)(U + grow * RWORDS + gq * 4)     = qu;
        };
        auto compute = [&](int s) {
            uint32_t so = (uint32_t)s * (GU_STAGEW * 4);
            #pragma unroll
            for (int sub = 0; sub < 2; sub++) {
                uint32_t soo = so + sub * 32;
                uint32_t a0[4], a1[4], g0[4], g1[4], u0[4], u1[4];
                ldm4(a0, adrA0 + soo); ldm4(a1, adrA1 + soo);
                ldm4(g0, adrG0 + soo); ldm4(g1, adrG1 + soo);
                ldm4(u0, adrU0 + soo); ldm4(u1, adrU1 + soo);
                #pragma unroll
                for (int p = 0; p < 2; p++) {
                    const uint32_t* gg = p ? g1 : g0;
                    const uint32_t* uu = p ? u1 : u0;
                    #pragma unroll
                    for (int q = 0; q < 2; q++) {
                        int nt = p * 2 + q;
                        mma_f16(accG[0][nt], a0, gg[q * 2], gg[q * 2 + 1]);
                        mma_f16(accG[1][nt], a1, gg[q * 2], gg[q * 2 + 1]);
                        mma_f16(accU[0][nt], a0, uu[q * 2], uu[q * 2 + 1]);
                        mma_f16(accU[1][nt], a1, uu[q * 2], uu[q * 2 + 1]);
                    }
                }
            }
        };

        const int NC = H / 32;   // 32
        ldc(0); sts(0);
        __syncthreads();
        ldc(1);
        for (int c = 0; c < NC; c++) {
            compute(c & 1);
            if (c + 1 < NC) sts((c + 1) & 1);
            __syncthreads();
            if (c + 2 < NC) ldc(c + 2);
        }

        // epilogue: h = silu(gate)*up*route_w -> half2 words
        #pragma unroll
        for (int mt = 0; mt < 2; mt++) {
            #pragma unroll
            for (int rh = 0; rh < 2; rh++) {
                int r = wm * 32 + mt * 16 + gid + rh * 8;
                int said = said_s[r];
                if (said < 0) continue;
                float wv = swt_s[r];
                uint32_t* hp = g_hbufw + (size_t)(gbase + r) * (M / 2)
                             + ((m0 + wn * 32) >> 1) + tig;
                #pragma unroll
                for (int nt = 0; nt < 4; nt++) {
                    float g0 = accG[mt][nt][rh * 2 + 0];
                    float g1 = accG[mt][nt][rh * 2 + 1];
                    float u0 = accU[mt][nt][rh * 2 + 0];
                    float u1 = accU[mt][nt][rh * 2 + 1];
                    float o0 = (g0 / (1.f + __expf(-g0))) * u0 * wv;
                    float o1 = (g1 / (1.f + __expf(-g1))) * u1 * wv;
                    hp[nt * 4] = f2h2(o0, o1);
                }
            }
        }
    }
}

// ------------------------- down fp16 mma GEMM ------------------------------
// persistent; 256 threads, warps 2x4; block 128 rows x 128 h-cols; warp 64x32
#define DN_STAGEW 5120
#define DN_SMEMB  (2 * DN_STAGEW * 4)      // 40960 bytes

__global__ void __launch_bounds__(256, 2)
down_mma(const float* __restrict__ wd) {
    extern __shared__ uint32_t sm[];
    __shared__ int styp[E + 1];
    __shared__ int said_s[128];

    int tid = threadIdx.x, lane = tid & 31, wid = tid >> 5;
    int gid = lane >> 2, tig = lane & 3;
    int wm = wid & 1, wn = wid >> 1;

    if (tid <= E) styp[tid] = g_typre[tid];
    __syncthreads();
    int totalW = styp[E] * 8;

    uint32_t sbase = smem_u32(sm);
    int a_ro = lane & 15;
    int a_kw = (lane >> 4) * 16;
    uint32_t adrA[4];
    #pragma unroll
    for (int mt = 0; mt < 4; mt++)
        adrA[mt] = sbase + (uint32_t)(wm * 64 + mt * 16 + a_ro) * RBYTES + a_kw;
    int b_ro = (lane & 7) + ((lane & 16) >> 1);
    int b_kw = (lane & 8) ? 16 : 0;
    uint32_t adrW0 = sbase + 128 * RBYTES + (uint32_t)(wn * 32 + b_ro) * RBYTES + b_kw;
    uint32_t adrW1 = adrW0 + 16 * RBYTES;

    int arow = tid >> 1, ah = tid & 1;

    for (int w = blockIdx.x; w < totalW; w += gridDim.x) {
        int ytl = w >> 3, xt = w & 7;
        int e = 0;
        while (styp[e + 1] <= ytl) e++;
        int t0 = (ytl - styp[e]) * 128;
        int h0 = xt * 128;
        int n  = g_count[e];
        int gbase = g_off[e] + t0;

        __syncthreads();
        if (tid < 128) {
            int slot = t0 + tid;
            said_s[tid] = (slot < n) ? g_tok[e * T + slot] : -1;
        }
        __syncthreads();

        const uint32_t* abw = g_hbufw + (size_t)(gbase + arow) * (M / 2) + ah * 8;
        const float*    wp  = wd + ((size_t)e * H + h0 + arow) * M + ah * 16;

        float acc[4][4][4];
        #pragma unroll
        for (int i = 0; i < 4; i++)
            #pragma unroll
            for (int j = 0; j < 4; j++)
                #pragma unroll
                for (int q = 0; q < 4; q++) acc[i][j][q] = 0.f;

        uint4 qa0, qa1, qw0, qw1;
        auto ldc = [&](int c) {
            qa0 = *(const uint4*)(abw + c * 16);
            qa1 = *(const uint4*)(abw + c * 16 + 4);
            float4 f0 = *(const float4*)(wp + c * 32);
            float4 f1 = *(const float4*)(wp + c * 32 + 4);
            float4 f2 = *(const float4*)(wp + c * 32 + 8);
            float4 f3 = *(const float4*)(wp + c * 32 + 12);
            qw0 = pack4(f0, f1); qw1 = pack4(f2, f3);
        };
        auto sts = [&](int s) {
            uint32_t* st = sm + s * DN_STAGEW;
            uint32_t* A = st;
            uint32_t* W = st + 128 * RWORDS;
            *(uint4*)(A + arow * RWORDS + ah * 8)     = qa0;
            *(uint4*)(A + arow * RWORDS + ah * 8 + 4) = qa1;
            *(uint4*)(W + arow * RWORDS + ah * 8)     = qw0;
            *(uint4*)(W + arow * RWORDS + ah * 8 + 4) = qw1;
        };
        auto compute = [&](int s) {
            uint32_t so = (uint32_t)s * (DN_STAGEW * 4);
            #pragma unroll
            for (int sub = 0; sub < 2; sub++) {
                uint32_t soo = so + sub * 32;
                uint32_t a[4][4], w0[4], w1[4];
                #pragma unroll
                for (int mt = 0; mt < 4; mt++) ldm4(a[mt], adrA[mt] + soo);
                ldm4(w0, adrW0 + soo); ldm4(w1, adrW1 + soo);
                #pragma unroll
                for (int p = 0; p < 2; p++) {
                    const uint32_t* ww = p ? w1 : w0;
                    #pragma unroll
                    for (int q = 0; q < 2; q++) {
                        int nt = p * 2 + q;
                        #pragma unroll
                        for (int mt = 0; mt < 4; mt++)
                            mma_f16(acc[mt][nt], a[mt], ww[q * 2], ww[q * 2 + 1]);
                    }
                }
            }
        };

        const int NC = M / 32;   // 16
        ldc(0); sts(0);
        __syncthreads();
        ldc(1);
        for (int c = 0; c < NC; c++) {
            compute(c & 1);
            if (c + 1 < NC) sts((c + 1) & 1);
            __syncthreads();
            if (c + 2 < NC) ldc(c + 2);
        }

        #pragma unroll
        for (int mt = 0; mt < 4; mt++) {
            #pragma unroll
            for (int rh = 0; rh < 2; rh++) {
                int r = wm * 64 + mt * 16 + gid + rh * 8;
                int aid = said_s[r];
                if (aid < 0) continue;
                float* op = g_part + (size_t)aid * H + h0 + wn * 32;
                #pragma unroll
                for (int nt = 0; nt < 4; nt++) {
                    float2 o;
                    o.x = acc[mt][nt][rh * 2 + 0];
                    o.y = acc[mt][nt][rh * 2 + 1];
                    *(float2*)(op + nt * 8 + tig * 2) = o;
                }
            }
        }
    }
}

// ------------------------- final reduce ------------------------------------
__global__ void reduce_kernel(float* __restrict__ out) {
    int i = blockIdx.x * 256 + threadIdx.x;
    int t = i >> 8;
    int h4 = i & 255;
    const float4* p = (const float4*)(g_part + (size_t)t * 4 * H) + h4;
    float4 a = p[0], b = p[256], c = p[512], d = p[768];
    float4 o;
    o.x = a.x + b.x + c.x + d.x;
    o.y = a.y + b.y + c.y + d.y;
    o.z = a.z + b.z + c.z + d.z;
    o.w = a.w + b.w + c.w + d.w;
    ((float4*)out)[i] = o;
}

// ------------------------- launcher ----------------------------------------
extern "C" void kernel_launch(void* const* d_in, const int* in_sizes, int n_in,
                              void* d_out, int out_size) {
    const float* x      = (const float*)d_in[0];
    const float* gate_w = (const float*)d_in[1];
    const float* w_gate = (const float*)d_in[2];
    const float* w_up   = (const float*)d_in[3];
    const float* w_down = (const float*)d_in[4];
    float* out = (float*)d_out;

    cudaFuncSetAttribute(gateup_mma, cudaFuncAttributeMaxDynamicSharedMemorySize, GU_SMEMB);
    cudaFuncSetAttribute(down_mma,   cudaFuncAttributeMaxDynamicSharedMemorySize, DN_SMEMB);

    zero_counts<<<1, 32>>>();
    router_kernel<<<T, 128>>>(x, gate_w);
    scan_kernel<<<1, 32>>>();
    gateup_mma<<<296, 256, GU_SMEMB>>>(x, w_gate, w_up);
    down_mma<<<296, 256, DN_SMEMB>>>(w_down);
    reduce_kernel<<<T * H / 4 / 256, 256>>>(out);
}

// round 11
// speedup vs baseline: 1.2071x; 1.2071x over previous
#include <cuda_runtime.h>
#include <cuda_fp16.h>
#include <math.h>
#include <stdint.h>

#define T 2048
#define H 1024
#define M 512
#define E 32
#define TOPK 4
#define NROWS (T * TOPK)
#define PROWS (NROWS + 128)

// ------------------------- static device scratch ---------------------------
__device__ int      g_count[E];
__device__ int      g_off[E];
__device__ int      g_typre[E + 1];
__device__ int      g_tok[E * T];
__device__ float    g_wt[E * T];
__device__ uint32_t g_hbufw[(size_t)PROWS * M / 2];   // half2 words
__device__ float    g_part[(size_t)NROWS * H];
// fp16 copies (filled by cvt_kernel each run)
__device__ __half   g_xh[(size_t)T * H];
__device__ __half   g_wgh[(size_t)E * M * H];
__device__ __half   g_wuh[(size_t)E * M * H];
__device__ __half   g_wdh[(size_t)E * H * M];

// ------------------------- helpers -----------------------------------------
__device__ __forceinline__ uint32_t smem_u32(const void* p) {
    return (uint32_t)__cvta_generic_to_shared(p);
}
__device__ __forceinline__ uint32_t f2h2(float a, float b) {
    uint32_t r;
    asm("cvt.rn.f16x2.f32 %0, %1, %2;" : "=r"(r) : "f"(b), "f"(a));
    return r;
}
__device__ __forceinline__ uint4 pack4(float4 a, float4 b) {
    uint4 o;
    o.x = f2h2(a.x, a.y); o.y = f2h2(a.z, a.w);
    o.z = f2h2(b.x, b.y); o.w = f2h2(b.z, b.w);
    return o;
}
__device__ __forceinline__ void ldm4(uint32_t* r, uint32_t addr) {
    asm volatile("ldmatrix.sync.aligned.m8n8.x4.shared.b16 {%0,%1,%2,%3}, [%4];"
        : "=r"(r[0]), "=r"(r[1]), "=r"(r[2]), "=r"(r[3]) : "r"(addr));
}
__device__ __forceinline__ void mma_f16(float* c, const uint32_t* a, uint32_t b0, uint32_t b1) {
    asm volatile("mma.sync.aligned.m16n8k16.row.col.f32.f16.f16.f32 "
        "{%0,%1,%2,%3}, {%4,%5,%6,%7}, {%8,%9}, {%0,%1,%2,%3};"
        : "+f"(c[0]), "+f"(c[1]), "+f"(c[2]), "+f"(c[3])
        : "r"(a[0]), "r"(a[1]), "r"(a[2]), "r"(a[3]), "r"(b0), "r"(b1));
}
__device__ __forceinline__ void cp16(uint32_t dst, const void* src, int sz) {
    asm volatile("cp.async.cg.shared.global [%0], [%1], 16, %2;"
        :: "r"(dst), "l"(src), "r"(sz) : "memory");
}
#define CP_COMMIT() asm volatile("cp.async.commit_group;" ::: "memory")
#define CP_WAIT(n)  asm volatile("cp.async.wait_group %0;" :: "n"(n) : "memory")

// smem row geometry: k32 chunk = 64B fp16 data + 16B pad = 80 bytes
#define RWORDS 20
#define RBYTES 80

// ------------------------- small kernels -----------------------------------
__global__ void zero_counts() { if (threadIdx.x < E) g_count[threadIdx.x] = 0; }

// fp32 -> fp16 streaming convert (8 floats per thread)
__global__ void cvt_kernel(const float4* __restrict__ src, uint4* __restrict__ dst, int n) {
    int i = blockIdx.x * blockDim.x + threadIdx.x;
    if (i >= n) return;
    float4 a = src[2 * i], b = src[2 * i + 1];
    dst[i] = pack4(a, b);
}

__global__ void router_kernel(const float* __restrict__ x,
                              const float* __restrict__ gate_w) {
    __shared__ float xs[H];
    __shared__ float logits[E];
    int t = blockIdx.x;
    const float* xr = x + (size_t)t * H;
    for (int i = threadIdx.x; i < H; i += blockDim.x) xs[i] = xr[i];
    __syncthreads();
    int warp = threadIdx.x >> 5, lane = threadIdx.x & 31;
    for (int e = warp; e < E; e += 4) {
        const float* w = gate_w + (size_t)e * H;
        float s = 0.f;
        for (int i = lane; i < H; i += 32) s += xs[i] * w[i];
        #pragma unroll
        for (int o = 16; o > 0; o >>= 1) s += __shfl_xor_sync(0xffffffffu, s, o);
        if (lane == 0) logits[e] = s;
    }
    __syncthreads();
    if (threadIdx.x == 0) {
        int ids[TOPK]; float vals[TOPK];
        unsigned used = 0;
        for (int k = 0; k < TOPK; k++) {
            float best = -INFINITY; int bi = 0;
            for (int e = 0; e < E; e++)
                if (!((used >> e) & 1u) && logits[e] > best) { best = logits[e]; bi = e; }
            used |= (1u << bi); ids[k] = bi; vals[k] = best;
        }
        float mx = vals[0], se = 0.f, w4[TOPK];
        for (int k = 0; k < TOPK; k++) { w4[k] = expf(vals[k] - mx); se += w4[k]; }
        float inv = 1.0f / se;
        for (int k = 0; k < TOPK; k++) {
            int e = ids[k];
            int pos = atomicAdd(&g_count[e], 1);
            g_tok[e * T + pos] = t * TOPK + k;
            g_wt[e * T + pos] = w4[k] * inv;
        }
    }
}

__global__ void scan_kernel() {
    int lane = threadIdx.x;
    int c = g_count[lane];
    int ex = c;
    #pragma unroll
    for (int o = 1; o < 32; o <<= 1) {
        int v = __shfl_up_sync(0xffffffffu, ex, o);
        if (lane >= o) ex += v;
    }
    g_off[lane] = ex - c;
    int ty = (c + 127) >> 7;
    int tp = ty;
    #pragma unroll
    for (int o = 1; o < 32; o <<= 1) {
        int v = __shfl_up_sync(0xffffffffu, tp, o);
        if (lane >= o) tp += v;
    }
    g_typre[lane] = tp - ty;
    if (lane == 31) g_typre[E] = tp;
}

// ------------------------- gate/up fp16 mma GEMM ---------------------------
// persistent; 256 threads, warps 4x2; block 128 rows x 64 m-cols; K chunk 32
// 4-stage cp.async pipeline; stage = 128 A + 64 G + 64 U rows x 80B
#define GU_STAGEW 5120
#define GU_STAGEB (GU_STAGEW * 4)          // 20480 bytes
#define GU_SMEMB  (4 * GU_STAGEB)          // 81920 bytes

__global__ void __launch_bounds__(256, 2)
gateup_mma() {
    extern __shared__ uint32_t sm[];
    __shared__ int   styp[E + 1];
    __shared__ int   said_s[128];
    __shared__ float swt_s[128];

    int tid = threadIdx.x, lane = tid & 31, wid = tid >> 5;
    int gid = lane >> 2, tig = lane & 3;
    int wm = wid & 3, wn = wid >> 2;

    if (tid <= E) styp[tid] = g_typre[tid];
    __syncthreads();
    int totalW = styp[E] * 8;

    uint32_t sbase = smem_u32(sm);
    int a_ro = lane & 15;
    int a_kw = (lane >> 4) * 16;
    uint32_t adrA0 = sbase + (uint32_t)(wm * 32 + a_ro) * RBYTES + a_kw;
    uint32_t adrA1 = adrA0 + 16 * RBYTES;
    int b_ro = (lane & 7) + ((lane & 16) >> 1);
    int b_kw = (lane & 8) ? 16 : 0;
    uint32_t adrG0 = sbase + 128 * RBYTES + (uint32_t)(wn * 32 + b_ro) * RBYTES + b_kw;
    uint32_t adrG1 = adrG0 + 16 * RBYTES;
    uint32_t adrU0 = adrG0 + 64 * RBYTES;
    uint32_t adrU1 = adrU0 + 16 * RBYTES;

    // cp.async loader mapping
    int ar = tid >> 1, aj = (tid & 1) * 2;    // A: row 0..127, 2 x 16B (j, j+1)
    int gr = tid >> 2, gj = tid & 3;          // G/U: row 0..63, 1 x 16B each

    for (int w = blockIdx.x; w < totalW; w += gridDim.x) {
        int ytl = w >> 3, xt = w & 7;
        int e = 0;
        while (styp[e + 1] <= ytl) e++;
        int t0 = (ytl - styp[e]) * 128;
        int m0 = xt * 64;
        int n  = g_count[e];
        int gbase = g_off[e] + t0;

        __syncthreads();
        if (tid < 128) {
            int slot = t0 + tid;
            bool v = slot < n;
            said_s[tid] = v ? g_tok[e * T + slot] : -1;
            swt_s[tid]  = v ? g_wt[e * T + slot] : 0.f;
        }
        __syncthreads();

        int aid_a = said_s[ar];
        int apred = (aid_a >= 0) ? 16 : 0;
        const char* asrc0 = (const char*)(g_xh + (size_t)((aid_a < 0 ? 0 : aid_a) >> 2) * H) + aj * 16;
        const char* gsrc0 = (const char*)(g_wgh + ((size_t)e * M + m0 + gr) * H) + gj * 16;
        const char* usrc0 = (const char*)(g_wuh + ((size_t)e * M + m0 + gr) * H) + gj * 16;

        float accG[2][4][4], accU[2][4][4];
        #pragma unroll
        for (int i = 0; i < 2; i++)
            #pragma unroll
            for (int j = 0; j < 4; j++)
                #pragma unroll
                for (int q = 0; q < 4; q++) { accG[i][j][q] = 0.f; accU[i][j][q] = 0.f; }

        auto issue = [&](int c, int s) {
            uint32_t st = sbase + (uint32_t)s * GU_STAGEB;
            const char* as = asrc0 + c * 64;
            cp16(st + ar * RBYTES + aj * 16,      as,      apred);
            cp16(st + ar * RBYTES + aj * 16 + 16, as + 16, apred);
            cp16(st + 128 * RBYTES + gr * RBYTES + gj * 16, gsrc0 + c * 64, 16);
            cp16(st + 192 * RBYTES + gr * RBYTES + gj * 16, usrc0 + c * 64, 16);
        };
        auto compute = [&](int s) {
            uint32_t so = (uint32_t)s * GU_STAGEB;
            #pragma unroll
            for (int sub = 0; sub < 2; sub++) {
                uint32_t soo = so + sub * 32;
                uint32_t a0[4], a1[4], g0[4], g1[4], u0[4], u1[4];
                ldm4(a0, adrA0 + soo); ldm4(a1, adrA1 + soo);
                ldm4(g0, adrG0 + soo); ldm4(g1, adrG1 + soo);
                ldm4(u0, adrU0 + soo); ldm4(u1, adrU1 + soo);
                #pragma unroll
                for (int p = 0; p < 2; p++) {
                    const uint32_t* gg = p ? g1 : g0;
                    const uint32_t* uu = p ? u1 : u0;
                    #pragma unroll
                    for (int q = 0; q < 2; q++) {
                        int nt = p * 2 + q;
                        mma_f16(accG[0][nt], a0, gg[q * 2], gg[q * 2 + 1]);
                        mma_f16(accG[1][nt], a1, gg[q * 2], gg[q * 2 + 1]);
                        mma_f16(accU[0][nt], a0, uu[q * 2], uu[q * 2 + 1]);
                        mma_f16(accU[1][nt], a1, uu[q * 2], uu[q * 2 + 1]);
                    }
                }
            }
        };

        const int NC = H / 32;   // 32
        issue(0, 0); CP_COMMIT();
        issue(1, 1); CP_COMMIT();
        issue(2, 2); CP_COMMIT();
        CP_WAIT(2);
        __syncthreads();
        for (int c = 0; c < NC; c++) {
            compute(c & 3);
            if (c + 3 < NC) issue(c + 3, (c + 3) & 3);
            CP_COMMIT();
            CP_WAIT(2);
            __syncthreads();
        }

        // epilogue: h = silu(gate)*up*route_w -> half2 words
        #pragma unroll
        for (int mt = 0; mt < 2; mt++) {
            #pragma unroll
            for (int rh = 0; rh < 2; rh++) {
                int r = wm * 32 + mt * 16 + gid + rh * 8;
                int said = said_s[r];
                if (said < 0) continue;
                float wv = swt_s[r];
                uint32_t* hp = g_hbufw + (size_t)(gbase + r) * (M / 2)
                             + ((m0 + wn * 32) >> 1) + tig;
                #pragma unroll
                for (int nt = 0; nt < 4; nt++) {
                    float g0 = accG[mt][nt][rh * 2 + 0];
                    float g1 = accG[mt][nt][rh * 2 + 1];
                    float u0 = accU[mt][nt][rh * 2 + 0];
                    float u1 = accU[mt][nt][rh * 2 + 1];
                    float o0 = (g0 / (1.f + __expf(-g0))) * u0 * wv;
                    float o1 = (g1 / (1.f + __expf(-g1))) * u1 * wv;
                    hp[nt * 4] = f2h2(o0, o1);
                }
            }
        }
    }
}

// ------------------------- down fp16 mma GEMM ------------------------------
// persistent; 256 threads, warps 2x4; block 128 rows x 128 h-cols; warp 64x32
#define DN_STAGEW 5120
#define DN_STAGEB (DN_STAGEW * 4)
#define DN_SMEMB  (4 * DN_STAGEB)          // 81920 bytes

__global__ void __launch_bounds__(256, 2)
down_mma() {
    extern __shared__ uint32_t sm[];
    __shared__ int styp[E + 1];
    __shared__ int said_s[128];

    int tid = threadIdx.x, lane = tid & 31, wid = tid >> 5;
    int gid = lane >> 2, tig = lane & 3;
    int wm = wid & 1, wn = wid >> 1;

    if (tid <= E) styp[tid] = g_typre[tid];
    __syncthreads();
    int totalW = styp[E] * 8;

    uint32_t sbase = smem_u32(sm);
    int a_ro = lane & 15;
    int a_kw = (lane >> 4) * 16;
    uint32_t adrA[4];
    #pragma unroll
    for (int mt = 0; mt < 4; mt++)
        adrA[mt] = sbase + (uint32_t)(wm * 64 + mt * 16 + a_ro) * RBYTES + a_kw;
    int b_ro = (lane & 7) + ((lane & 16) >> 1);
    int b_kw = (lane & 8) ? 16 : 0;
    uint32_t adrW0 = sbase + 128 * RBYTES + (uint32_t)(wn * 32 + b_ro) * RBYTES + b_kw;
    uint32_t adrW1 = adrW0 + 16 * RBYTES;

    int ar = tid >> 1, aj = (tid & 1) * 2;    // rows 0..127, 2 x 16B each for A and W

    for (int w = blockIdx.x; w < totalW; w += gridDim.x) {
        int ytl = w >> 3, xt = w & 7;
        int e = 0;
        while (styp[e + 1] <= ytl) e++;
        int t0 = (ytl - styp[e]) * 128;
        int h0 = xt * 128;
        int n  = g_count[e];
        int gbase = g_off[e] + t0;

        __syncthreads();
        if (tid < 128) {
            int slot = t0 + tid;
            said_s[tid] = (slot < n) ? g_tok[e * T + slot] : -1;
        }
        __syncthreads();

        const char* asrc0 = (const char*)(g_hbufw + (size_t)(gbase + ar) * (M / 2)) + aj * 16;
        const char* wsrc0 = (const char*)(g_wdh + ((size_t)e * H + h0 + ar) * M) + aj * 16;

        float acc[4][4][4];
        #pragma unroll
        for (int i = 0; i < 4; i++)
            #pragma unroll
            for (int j = 0; j < 4; j++)
                #pragma unroll
                for (int q = 0; q < 4; q++) acc[i][j][q] = 0.f;

        auto issue = [&](int c, int s) {
            uint32_t st = sbase + (uint32_t)s * DN_STAGEB;
            const char* as = asrc0 + c * 64;
            const char* ws = wsrc0 + c * 64;
            cp16(st + ar * RBYTES + aj * 16,      as,      16);
            cp16(st + ar * RBYTES + aj * 16 + 16, as + 16, 16);
            cp16(st + 128 * RBYTES + ar * RBYTES + aj * 16,      ws,      16);
            cp16(st + 128 * RBYTES + ar * RBYTES + aj * 16 + 16, ws + 16, 16);
        };
        auto compute = [&](int s) {
            uint32_t so = (uint32_t)s * DN_STAGEB;
            #pragma unroll
            for (int sub = 0; sub < 2; sub++) {
                uint32_t soo = so + sub * 32;
                uint32_t a[4][4], w0[4], w1[4];
                #pragma unroll
                for (int mt = 0; mt < 4; mt++) ldm4(a[mt], adrA[mt] + soo);
                ldm4(w0, adrW0 + soo); ldm4(w1, adrW1 + soo);
                #pragma unroll
                for (int p = 0; p < 2; p++) {
                    const uint32_t* ww = p ? w1 : w0;
                    #pragma unroll
                    for (int q = 0; q < 2; q++) {
                        int nt = p * 2 + q;
                        #pragma unroll
                        for (int mt = 0; mt < 4; mt++)
                            mma_f16(acc[mt][nt], a[mt], ww[q * 2], ww[q * 2 + 1]);
                    }
                }
            }
        };

        const int NC = M / 32;   // 16
        issue(0, 0); CP_COMMIT();
        issue(1, 1); CP_COMMIT();
        issue(2, 2); CP_COMMIT();
        CP_WAIT(2);
        __syncthreads();
        for (int c = 0; c < NC; c++) {
            compute(c & 3);
            if (c + 3 < NC) issue(c + 3, (c + 3) & 3);
            CP_COMMIT();
            CP_WAIT(2);
            __syncthreads();
        }

        #pragma unroll
        for (int mt = 0; mt < 4; mt++) {
            #pragma unroll
            for (int rh = 0; rh < 2; rh++) {
                int r = wm * 64 + mt * 16 + gid + rh * 8;
                int aid = said_s[r];
                if (aid < 0) continue;
                float* op = g_part + (size_t)aid * H + h0 + wn * 32;
                #pragma unroll
                for (int nt = 0; nt < 4; nt++) {
                    float2 o;
                    o.x = acc[mt][nt][rh * 2 + 0];
                    o.y = acc[mt][nt][rh * 2 + 1];
                    *(float2*)(op + nt * 8 + tig * 2) = o;
                }
            }
        }
    }
}

// ------------------------- final reduce ------------------------------------
__global__ void reduce_kernel(float* __restrict__ out) {
    int i = blockIdx.x * 256 + threadIdx.x;
    int t = i >> 8;
    int h4 = i & 255;
    const float4* p = (const float4*)(g_part + (size_t)t * 4 * H) + h4;
    float4 a = p[0], b = p[256], c = p[512], d = p[768];
    float4 o;
    o.x = a.x + b.x + c.x + d.x;
    o.y = a.y + b.y + c.y + d.y;
    o.z = a.z + b.z + c.z + d.z;
    o.w = a.w + b.w + c.w + d.w;
    ((float4*)out)[i] = o;
}

// ------------------------- launcher ----------------------------------------
extern "C" void kernel_launch(void* const* d_in, const int* in_sizes, int n_in,
                              void* d_out, int out_size) {
    const float* x      = (const float*)d_in[0];
    const float* gate_w = (const float*)d_in[1];
    const float* w_gate = (const float*)d_in[2];
    const float* w_up   = (const float*)d_in[3];
    const float* w_down = (const float*)d_in[4];
    float* out = (float*)d_out;

    cudaFuncSetAttribute(gateup_mma, cudaFuncAttributeMaxDynamicSharedMemorySize, GU_SMEMB);
    cudaFuncSetAttribute(down_mma,   cudaFuncAttributeMaxDynamicSharedMemorySize, DN_SMEMB);

    __half *xh, *wgh, *wuh, *wdh;
    cudaGetSymbolAddress((void**)&xh,  g_xh);
    cudaGetSymbolAddress((void**)&wgh, g_wgh);
    cudaGetSymbolAddress((void**)&wuh, g_wuh);
    cudaGetSymbolAddress((void**)&wdh, g_wdh);

    const int NW8 = E * M * H / 8;       // 2097152
    const int NX8 = T * H / 8;           // 262144
    cvt_kernel<<<NX8 / 256, 256>>>((const float4*)x,      (uint4*)xh,  NX8);
    cvt_kernel<<<NW8 / 256, 256>>>((const float4*)w_gate, (uint4*)wgh, NW8);
    cvt_kernel<<<NW8 / 256, 256>>>((const float4*)w_up,   (uint4*)wuh, NW8);
    cvt_kernel<<<NW8 / 256, 256>>>((const float4*)w_down, (uint4*)wdh, NW8);

    zero_counts<<<1, 32>>>();
    router_kernel<<<T, 128>>>(x, gate_w);
    scan_kernel<<<1, 32>>>();
    gateup_mma<<<296, 256, GU_SMEMB>>>();
    down_mma<<<296, 256, DN_SMEMB>>>();
    reduce_kernel<<<T * H / 4 / 256, 256>>>(out);
}

// round 12
// speedup vs baseline: 1.2520x; 1.0372x over previous
#include <cuda_runtime.h>
#include <cuda_fp16.h>
#include <math.h>
#include <stdint.h>

#define T 2048
#define H 1024
#define M 512
#define E 32
#define TOPK 4
#define NROWS (T * TOPK)
#define PROWS (NROWS + 128)

// ------------------------- static device scratch ---------------------------
__device__ int      g_count[E];
__device__ int      g_off[E];
__device__ int      g_typre[E + 1];
__device__ int      g_tok[E * T];
__device__ float    g_wt[E * T];
__device__ uint32_t g_hbufw[(size_t)PROWS * M / 2];   // half2 words
// fp16 copies (filled by cvt_all each run)
__device__ __half   g_xh[(size_t)T * H];
__device__ __half   g_wgh[(size_t)E * M * H];
__device__ __half   g_wuh[(size_t)E * M * H];
__device__ __half   g_wdh[(size_t)E * H * M];

// ------------------------- helpers -----------------------------------------
__device__ __forceinline__ uint32_t smem_u32(const void* p) {
    return (uint32_t)__cvta_generic_to_shared(p);
}
__device__ __forceinline__ uint32_t f2h2(float a, float b) {
    uint32_t r;
    asm("cvt.rn.f16x2.f32 %0, %1, %2;" : "=r"(r) : "f"(b), "f"(a));
    return r;
}
__device__ __forceinline__ uint4 pack4(float4 a, float4 b) {
    uint4 o;
    o.x = f2h2(a.x, a.y); o.y = f2h2(a.z, a.w);
    o.z = f2h2(b.x, b.y); o.w = f2h2(b.z, b.w);
    return o;
}
__device__ __forceinline__ void ldm4(uint32_t* r, uint32_t addr) {
    asm volatile("ldmatrix.sync.aligned.m8n8.x4.shared.b16 {%0,%1,%2,%3}, [%4];"
        : "=r"(r[0]), "=r"(r[1]), "=r"(r[2]), "=r"(r[3]) : "r"(addr));
}
__device__ __forceinline__ void mma_f16(float* c, const uint32_t* a, uint32_t b0, uint32_t b1) {
    asm volatile("mma.sync.aligned.m16n8k16.row.col.f32.f16.f16.f32 "
        "{%0,%1,%2,%3}, {%4,%5,%6,%7}, {%8,%9}, {%0,%1,%2,%3};"
        : "+f"(c[0]), "+f"(c[1]), "+f"(c[2]), "+f"(c[3])
        : "r"(a[0]), "r"(a[1]), "r"(a[2]), "r"(a[3]), "r"(b0), "r"(b1));
}
__device__ __forceinline__ void cp16(uint32_t dst, const void* src, int sz) {
    asm volatile("cp.async.cg.shared.global [%0], [%1], 16, %2;"
        :: "r"(dst), "l"(src), "r"(sz) : "memory");
}
#define CP_COMMIT() asm volatile("cp.async.commit_group;" ::: "memory")
#define CP_WAIT(n)  asm volatile("cp.async.wait_group %0;" :: "n"(n) : "memory")

// smem row geometry: k32 chunk = 64B fp16 data + 16B pad = 80 bytes
#define RWORDS 20
#define RBYTES 80

// ------------------------- small kernels -----------------------------------
// zero counters + output (out is poisoned by harness; down_mma atomically adds)
__global__ void zero_kernel(float* __restrict__ out) {
    int i = blockIdx.x * blockDim.x + threadIdx.x;
    if (i < E) g_count[i] = 0;
    float4 z = make_float4(0.f, 0.f, 0.f, 0.f);
    for (int j = i; j < T * H / 4; j += gridDim.x * blockDim.x)
        ((float4*)out)[j] = z;
}

// fused fp32->fp16 convert of x, w_gate, w_up, w_down (8 floats per thread)
#define NX8 (T * H / 8)          // 262144
#define NW8 (E * M * H / 8)      // 2097152
#define NCVT (NX8 + 3 * NW8)

__global__ void cvt_all(const float4* __restrict__ x,
                        const float4* __restrict__ wg,
                        const float4* __restrict__ wu,
                        const float4* __restrict__ wd) {
    int i = blockIdx.x * blockDim.x + threadIdx.x;
    if (i >= NCVT) return;
    const float4* src; uint4* dst; int k;
    if (i < NX8)                { src = x;  dst = (uint4*)g_xh;  k = i; }
    else if (i < NX8 + NW8)     { src = wg; dst = (uint4*)g_wgh; k = i - NX8; }
    else if (i < NX8 + 2 * NW8) { src = wu; dst = (uint4*)g_wuh; k = i - NX8 - NW8; }
    else                        { src = wd; dst = (uint4*)g_wdh; k = i - NX8 - 2 * NW8; }
    float4 a = src[2 * (size_t)k], b = src[2 * (size_t)k + 1];
    dst[k] = pack4(a, b);
}

__global__ void router_kernel(const float* __restrict__ x,
                              const float* __restrict__ gate_w) {
    __shared__ float xs[H];
    __shared__ float logits[E];
    int t = blockIdx.x;
    const float* xr = x + (size_t)t * H;
    for (int i = threadIdx.x; i < H; i += blockDim.x) xs[i] = xr[i];
    __syncthreads();
    int warp = threadIdx.x >> 5, lane = threadIdx.x & 31;
    for (int e = warp; e < E; e += 4) {
        const float* w = gate_w + (size_t)e * H;
        float s = 0.f;
        for (int i = lane; i < H; i += 32) s += xs[i] * w[i];
        #pragma unroll
        for (int o = 16; o > 0; o >>= 1) s += __shfl_xor_sync(0xffffffffu, s, o);
        if (lane == 0) logits[e] = s;
    }
    __syncthreads();
    if (threadIdx.x == 0) {
        int ids[TOPK]; float vals[TOPK];
        unsigned used = 0;
        for (int k = 0; k < TOPK; k++) {
            float best = -INFINITY; int bi = 0;
            for (int e = 0; e < E; e++)
                if (!((used >> e) & 1u) && logits[e] > best) { best = logits[e]; bi = e; }
            used |= (1u << bi); ids[k] = bi; vals[k] = best;
        }
        float mx = vals[0], se = 0.f, w4[TOPK];
        for (int k = 0; k < TOPK; k++) { w4[k] = expf(vals[k] - mx); se += w4[k]; }
        float inv = 1.0f / se;
        for (int k = 0; k < TOPK; k++) {
            int e = ids[k];
            int pos = atomicAdd(&g_count[e], 1);
            g_tok[e * T + pos] = t * TOPK + k;
            g_wt[e * T + pos] = w4[k] * inv;
        }
    }
}

__global__ void scan_kernel() {
    int lane = threadIdx.x;
    int c = g_count[lane];
    int ex = c;
    #pragma unroll
    for (int o = 1; o < 32; o <<= 1) {
        int v = __shfl_up_sync(0xffffffffu, ex, o);
        if (lane >= o) ex += v;
    }
    g_off[lane] = ex - c;
    int ty = (c + 127) >> 7;
    int tp = ty;
    #pragma unroll
    for (int o = 1; o < 32; o <<= 1) {
        int v = __shfl_up_sync(0xffffffffu, tp, o);
        if (lane >= o) tp += v;
    }
    g_typre[lane] = tp - ty;
    if (lane == 31) g_typre[E] = tp;
}

// ------------------------- gate/up fp16 mma GEMM ---------------------------
// persistent; 256 threads, warps 4x2; block 128 rows x 64 m-cols; K chunk 32
// 4-stage cp.async pipeline; stage = 128 A + 64 G + 64 U rows x 80B
#define GU_STAGEW 5120
#define GU_STAGEB (GU_STAGEW * 4)          // 20480 bytes
#define GU_SMEMB  (4 * GU_STAGEB)          // 81920 bytes

__global__ void __launch_bounds__(256, 2)
gateup_mma() {
    extern __shared__ uint32_t sm[];
    __shared__ int   styp[E + 1];
    __shared__ int   said_s[128];
    __shared__ float swt_s[128];

    int tid = threadIdx.x, lane = tid & 31, wid = tid >> 5;
    int gid = lane >> 2, tig = lane & 3;
    int wm = wid & 3, wn = wid >> 2;

    if (tid <= E) styp[tid] = g_typre[tid];
    __syncthreads();
    int totalW = styp[E] * 8;

    uint32_t sbase = smem_u32(sm);
    int a_ro = lane & 15;
    int a_kw = (lane >> 4) * 16;
    uint32_t adrA0 = sbase + (uint32_t)(wm * 32 + a_ro) * RBYTES + a_kw;
    uint32_t adrA1 = adrA0 + 16 * RBYTES;
    int b_ro = (lane & 7) + ((lane & 16) >> 1);
    int b_kw = (lane & 8) ? 16 : 0;
    uint32_t adrG0 = sbase + 128 * RBYTES + (uint32_t)(wn * 32 + b_ro) * RBYTES + b_kw;
    uint32_t adrG1 = adrG0 + 16 * RBYTES;
    uint32_t adrU0 = adrG0 + 64 * RBYTES;
    uint32_t adrU1 = adrU0 + 16 * RBYTES;

    int ar = tid >> 1, aj = (tid & 1) * 2;
    int gr = tid >> 2, gj = tid & 3;

    for (int w = blockIdx.x; w < totalW; w += gridDim.x) {
        int ytl = w >> 3, xt = w & 7;
        int e = 0;
        while (styp[e + 1] <= ytl) e++;
        int t0 = (ytl - styp[e]) * 128;
        int m0 = xt * 64;
        int n  = g_count[e];
        int gbase = g_off[e] + t0;

        __syncthreads();
        if (tid < 128) {
            int slot = t0 + tid;
            bool v = slot < n;
            said_s[tid] = v ? g_tok[e * T + slot] : -1;
            swt_s[tid]  = v ? g_wt[e * T + slot] : 0.f;
        }
        __syncthreads();

        int aid_a = said_s[ar];
        int apred = (aid_a >= 0) ? 16 : 0;
        const char* asrc0 = (const char*)(g_xh + (size_t)((aid_a < 0 ? 0 : aid_a) >> 2) * H) + aj * 16;
        const char* gsrc0 = (const char*)(g_wgh + ((size_t)e * M + m0 + gr) * H) + gj * 16;
        const char* usrc0 = (const char*)(g_wuh + ((size_t)e * M + m0 + gr) * H) + gj * 16;

        float accG[2][4][4], accU[2][4][4];
        #pragma unroll
        for (int i = 0; i < 2; i++)
            #pragma unroll
            for (int j = 0; j < 4; j++)
                #pragma unroll
                for (int q = 0; q < 4; q++) { accG[i][j][q] = 0.f; accU[i][j][q] = 0.f; }

        auto issue = [&](int c, int s) {
            uint32_t st = sbase + (uint32_t)s * GU_STAGEB;
            const char* as = asrc0 + c * 64;
            cp16(st + ar * RBYTES + aj * 16,      as,      apred);
            cp16(st + ar * RBYTES + aj * 16 + 16, as + 16, apred);
            cp16(st + 128 * RBYTES + gr * RBYTES + gj * 16, gsrc0 + c * 64, 16);
            cp16(st + 192 * RBYTES + gr * RBYTES + gj * 16, usrc0 + c * 64, 16);
        };
        auto compute = [&](int s) {
            uint32_t so = (uint32_t)s * GU_STAGEB;
            #pragma unroll
            for (int sub = 0; sub < 2; sub++) {
                uint32_t soo = so + sub * 32;
                uint32_t a0[4], a1[4], g0[4], g1[4], u0[4], u1[4];
                ldm4(a0, adrA0 + soo); ldm4(a1, adrA1 + soo);
                ldm4(g0, adrG0 + soo); ldm4(g1, adrG1 + soo);
                ldm4(u0, adrU0 + soo); ldm4(u1, adrU1 + soo);
                #pragma unroll
                for (int p = 0; p < 2; p++) {
                    const uint32_t* gg = p ? g1 : g0;
                    const uint32_t* uu = p ? u1 : u0;
                    #pragma unroll
                    for (int q = 0; q < 2; q++) {
                        int nt = p * 2 + q;
                        mma_f16(accG[0][nt], a0, gg[q * 2], gg[q * 2 + 1]);
                        mma_f16(accG[1][nt], a1, gg[q * 2], gg[q * 2 + 1]);
                        mma_f16(accU[0][nt], a0, uu[q * 2], uu[q * 2 + 1]);
                        mma_f16(accU[1][nt], a1, uu[q * 2], uu[q * 2 + 1]);
                    }
                }
            }
        };

        const int NC = H / 32;   // 32
        issue(0, 0); CP_COMMIT();
        issue(1, 1); CP_COMMIT();
        issue(2, 2); CP_COMMIT();
        CP_WAIT(2);
        __syncthreads();
        for (int c = 0; c < NC; c++) {
            compute(c & 3);
            if (c + 3 < NC) issue(c + 3, (c + 3) & 3);
            CP_COMMIT();
            CP_WAIT(2);
            __syncthreads();
        }

        // epilogue: h = silu(gate)*up*route_w -> half2 words
        #pragma unroll
        for (int mt = 0; mt < 2; mt++) {
            #pragma unroll
            for (int rh = 0; rh < 2; rh++) {
                int r = wm * 32 + mt * 16 + gid + rh * 8;
                int said = said_s[r];
                if (said < 0) continue;
                float wv = swt_s[r];
                uint32_t* hp = g_hbufw + (size_t)(gbase + r) * (M / 2)
                             + ((m0 + wn * 32) >> 1) + tig;
                #pragma unroll
                for (int nt = 0; nt < 4; nt++) {
                    float g0 = accG[mt][nt][rh * 2 + 0];
                    float g1 = accG[mt][nt][rh * 2 + 1];
                    float u0 = accU[mt][nt][rh * 2 + 0];
                    float u1 = accU[mt][nt][rh * 2 + 1];
                    float o0 = (g0 / (1.f + __expf(-g0))) * u0 * wv;
                    float o1 = (g1 / (1.f + __expf(-g1))) * u1 * wv;
                    hp[nt * 4] = f2h2(o0, o1);
                }
            }
        }
    }
}

// ------------------------- down fp16 mma GEMM ------------------------------
// persistent; 256 threads, warps 2x4; block 128 rows x 128 h-cols; warp 64x32
// epilogue: atomicAdd directly into out (replaces partials + reduce pass)
#define DN_STAGEW 5120
#define DN_STAGEB (DN_STAGEW * 4)
#define DN_SMEMB  (4 * DN_STAGEB)          // 81920 bytes

__global__ void __launch_bounds__(256, 2)
down_mma(float* __restrict__ out) {
    extern __shared__ uint32_t sm[];
    __shared__ int styp[E + 1];
    __shared__ int said_s[128];

    int tid = threadIdx.x, lane = tid & 31, wid = tid >> 5;
    int gid = lane >> 2, tig = lane & 3;
    int wm = wid & 1, wn = wid >> 1;

    if (tid <= E) styp[tid] = g_typre[tid];
    __syncthreads();
    int totalW = styp[E] * 8;

    uint32_t sbase = smem_u32(sm);
    int a_ro = lane & 15;
    int a_kw = (lane >> 4) * 16;
    uint32_t adrA[4];
    #pragma unroll
    for (int mt = 0; mt < 4; mt++)
        adrA[mt] = sbase + (uint32_t)(wm * 64 + mt * 16 + a_ro) * RBYTES + a_kw;
    int b_ro = (lane & 7) + ((lane & 16) >> 1);
    int b_kw = (lane & 8) ? 16 : 0;
    uint32_t adrW0 = sbase + 128 * RBYTES + (uint32_t)(wn * 32 + b_ro) * RBYTES + b_kw;
    uint32_t adrW1 = adrW0 + 16 * RBYTES;

    int ar = tid >> 1, aj = (tid & 1) * 2;

    for (int w = blockIdx.x; w < totalW; w += gridDim.x) {
        int ytl = w >> 3, xt = w & 7;
        int e = 0;
        while (styp[e + 1] <= ytl) e++;
        int t0 = (ytl - styp[e]) * 128;
        int h0 = xt * 128;
        int n  = g_count[e];
        int gbase = g_off[e] + t0;

        __syncthreads();
        if (tid < 128) {
            int slot = t0 + tid;
            said_s[tid] = (slot < n) ? g_tok[e * T + slot] : -1;
        }
        __syncthreads();

        const char* asrc0 = (const char*)(g_hbufw + (size_t)(gbase + ar) * (M / 2)) + aj * 16;
        const char* wsrc0 = (const char*)(g_wdh + ((size_t)e * H + h0 + ar) * M) + aj * 16;

        float acc[4][4][4];
        #pragma unroll
        for (int i = 0; i < 4; i++)
            #pragma unroll
            for (int j = 0; j < 4; j++)
                #pragma unroll
                for (int q = 0; q < 4; q++) acc[i][j][q] = 0.f;

        auto issue = [&](int c, int s) {
            uint32_t st = sbase + (uint32_t)s * DN_STAGEB;
            const char* as = asrc0 + c * 64;
            const char* ws = wsrc0 + c * 64;
            cp16(st + ar * RBYTES + aj * 16,      as,      16);
            cp16(st + ar * RBYTES + aj * 16 + 16, as + 16, 16);
            cp16(st + 128 * RBYTES + ar * RBYTES + aj * 16,      ws,      16);
            cp16(st + 128 * RBYTES + ar * RBYTES + aj * 16 + 16, ws + 16, 16);
        };
        auto compute = [&](int s) {
            uint32_t so = (uint32_t)s * DN_STAGEB;
            #pragma unroll
            for (int sub = 0; sub < 2; sub++) {
                uint32_t soo = so + sub * 32;
                uint32_t a[4][4], w0[4], w1[4];
                #pragma unroll
                for (int mt = 0; mt < 4; mt++) ldm4(a[mt], adrA[mt] + soo);
                ldm4(w0, adrW0 + soo); ldm4(w1, adrW1 + soo);
                #pragma unroll
                for (int p = 0; p < 2; p++) {
                    const uint32_t* ww = p ? w1 : w0;
                    #pragma unroll
                    for (int q = 0; q < 2; q++) {
                        int nt = p * 2 + q;
                        #pragma unroll
                        for (int mt = 0; mt < 4; mt++)
                            mma_f16(acc[mt][nt], a[mt], ww[q * 2], ww[q * 2 + 1]);
                    }
                }
            }
        };

        const int NC = M / 32;   // 16
        issue(0, 0); CP_COMMIT();
        issue(1, 1); CP_COMMIT();
        issue(2, 2); CP_COMMIT();
        CP_WAIT(2);
        __syncthreads();
        for (int c = 0; c < NC; c++) {
            compute(c & 3);
            if (c + 3 < NC) issue(c + 3, (c + 3) & 3);
            CP_COMMIT();
            CP_WAIT(2);
            __syncthreads();
        }

        #pragma unroll
        for (int mt = 0; mt < 4; mt++) {
            #pragma unroll
            for (int rh = 0; rh < 2; rh++) {
                int r = wm * 64 + mt * 16 + gid + rh * 8;
                int aid = said_s[r];
                if (aid < 0) continue;
                float* op = out + (size_t)(aid >> 2) * H + h0 + wn * 32 + tig * 2;
                #pragma unroll
                for (int nt = 0; nt < 4; nt++) {
                    atomicAdd(op + nt * 8,     acc[mt][nt][rh * 2 + 0]);
                    atomicAdd(op + nt * 8 + 1, acc[mt][nt][rh * 2 + 1]);
                }
            }
        }
    }
}

// ------------------------- launcher ----------------------------------------
extern "C" void kernel_launch(void* const* d_in, const int* in_sizes, int n_in,
                              void* d_out, int out_size) {
    const float* x      = (const float*)d_in[0];
    const float* gate_w = (const float*)d_in[1];
    const float* w_gate = (const float*)d_in[2];
    const float* w_up   = (const float*)d_in[3];
    const float* w_down = (const float*)d_in[4];
    float* out = (float*)d_out;

    cudaFuncSetAttribute(gateup_mma, cudaFuncAttributeMaxDynamicSharedMemorySize, GU_SMEMB);
    cudaFuncSetAttribute(down_mma,   cudaFuncAttributeMaxDynamicSharedMemorySize, DN_SMEMB);

    cvt_all<<<(NCVT + 255) / 256, 256>>>((const float4*)x, (const float4*)w_gate,
                                         (const float4*)w_up, (const float4*)w_down);
    zero_kernel<<<2048, 256>>>(out);
    router_kernel<<<T, 128>>>(x, gate_w);
    scan_kernel<<<1, 32>>>();
    gateup_mma<<<296, 256, GU_SMEMB>>>();
    down_mma<<<296, 256, DN_SMEMB>>>(out);
}

// round 13
// speedup vs baseline: 1.2866x; 1.0276x over previous
#include <cuda_runtime.h>
#include <cuda_fp16.h>
#include <math.h>
#include <stdint.h>

#define T 2048
#define H 1024
#define M 512
#define E 32
#define TOPK 4
#define NROWS (T * TOPK)
#define PROWS (NROWS + 128)

// ------------------------- static device scratch ---------------------------
__device__ int      g_count[E];
__device__ int      g_tok[E * T];
__device__ float    g_wt[E * T];
__device__ uint32_t g_hbufw[(size_t)PROWS * M / 2];   // half2 words
// fp16 copies
__device__ __half   g_xh[(size_t)T * H];
__device__ __half   g_wgh[(size_t)E * M * H];
__device__ __half   g_wuh[(size_t)E * M * H];
__device__ __half   g_wdh[(size_t)E * H * M];

// ------------------------- helpers -----------------------------------------
__device__ __forceinline__ uint32_t smem_u32(const void* p) {
    return (uint32_t)__cvta_generic_to_shared(p);
}
__device__ __forceinline__ uint32_t f2h2(float a, float b) {
    uint32_t r;
    asm("cvt.rn.f16x2.f32 %0, %1, %2;" : "=r"(r) : "f"(b), "f"(a));
    return r;
}
__device__ __forceinline__ uint4 pack4(float4 a, float4 b) {
    uint4 o;
    o.x = f2h2(a.x, a.y); o.y = f2h2(a.z, a.w);
    o.z = f2h2(b.x, b.y); o.w = f2h2(b.z, b.w);
    return o;
}
__device__ __forceinline__ void ldm4(uint32_t* r, uint32_t addr) {
    asm volatile("ldmatrix.sync.aligned.m8n8.x4.shared.b16 {%0,%1,%2,%3}, [%4];"
        : "=r"(r[0]), "=r"(r[1]), "=r"(r[2]), "=r"(r[3]) : "r"(addr));
}
__device__ __forceinline__ void mma_f16(float* c, const uint32_t* a, uint32_t b0, uint32_t b1) {
    asm volatile("mma.sync.aligned.m16n8k16.row.col.f32.f16.f16.f32 "
        "{%0,%1,%2,%3}, {%4,%5,%6,%7}, {%8,%9}, {%0,%1,%2,%3};"
        : "+f"(c[0]), "+f"(c[1]), "+f"(c[2]), "+f"(c[3])
        : "r"(a[0]), "r"(a[1]), "r"(a[2]), "r"(a[3]), "r"(b0), "r"(b1));
}
__device__ __forceinline__ void cp16(uint32_t dst, const void* src, int sz) {
    asm volatile("cp.async.cg.shared.global [%0], [%1], 16, %2;"
        :: "r"(dst), "l"(src), "r"(sz) : "memory");
}
#define CP_COMMIT() asm volatile("cp.async.commit_group;" ::: "memory")
#define CP_WAIT(n)  asm volatile("cp.async.wait_group %0;" :: "n"(n) : "memory")

// smem row geometry: k32 chunk = 64B fp16 data + 16B pad = 80 bytes
#define RWORDS 20
#define RBYTES 80

// in-block scan of g_count -> soff (row base) and styp (ytile prefix)
#define BLOCK_SCAN(soff, styp)                                             \
    if (wid == 0) {                                                        \
        int c = g_count[lane];                                             \
        int ex = c;                                                        \
        _Pragma("unroll")                                                  \
        for (int o = 1; o < 32; o <<= 1) {                                 \
            int v = __shfl_up_sync(0xffffffffu, ex, o);                    \
            if (lane >= o) ex += v;                                        \
        }                                                                  \
        soff[lane] = ex - c;                                               \
        int ty = (c + 127) >> 7;                                           \
        int tp = ty;                                                       \
        _Pragma("unroll")                                                  \
        for (int o = 1; o < 32; o <<= 1) {                                 \
            int v = __shfl_up_sync(0xffffffffu, tp, o);                    \
            if (lane >= o) tp += v;                                        \
        }                                                                  \
        styp[lane] = tp - ty;                                              \
        if (lane == 31) styp[E] = tp;                                      \
    }                                                                      \
    __syncthreads();

// ------------------------- fused cvt + zero kernel --------------------------
#define NW8  (E * M * H / 8)      // 2097152 per weight tensor
#define NZ4  (T * H / 4)          // 524288 output float4s
#define NTOT (3 * NW8 + NZ4)

__global__ void cvt_all(const float4* __restrict__ wg,
                        const float4* __restrict__ wu,
                        const float4* __restrict__ wd,
                        float* __restrict__ out) {
    int i = blockIdx.x * blockDim.x + threadIdx.x;
    if (i < E) g_count[i] = 0;
    if (i >= NTOT) return;
    if (i < 3 * NW8) {
        const float4* src; uint4* dst; int k;
        if (i < NW8)          { src = wg; dst = (uint4*)g_wgh; k = i; }
        else if (i < 2 * NW8) { src = wu; dst = (uint4*)g_wuh; k = i - NW8; }
        else                  { src = wd; dst = (uint4*)g_wdh; k = i - 2 * NW8; }
        float4 a = src[2 * (size_t)k], b = src[2 * (size_t)k + 1];
        dst[k] = pack4(a, b);
    } else {
        ((float4*)out)[i - 3 * NW8] = make_float4(0.f, 0.f, 0.f, 0.f);
    }
}

// ------------------------- router (+ x fp16 convert) ------------------------
__global__ void router_kernel(const float* __restrict__ x,
                              const float* __restrict__ gate_w) {
    __shared__ float xs[H];
    __shared__ float logits[E];
    int t = blockIdx.x;
    const float* xr = x + (size_t)t * H;
    for (int i = threadIdx.x; i < H; i += blockDim.x) xs[i] = xr[i];
    __syncthreads();
    // write fp16 copy of this row
    uint32_t* xh = (uint32_t*)(g_xh + (size_t)t * H);
    for (int i = threadIdx.x; i < H / 2; i += blockDim.x)
        xh[i] = f2h2(xs[2 * i], xs[2 * i + 1]);
    int warp = threadIdx.x >> 5, lane = threadIdx.x & 31;
    for (int e = warp; e < E; e += 4) {
        const float* w = gate_w + (size_t)e * H;
        float s = 0.f;
        for (int i = lane; i < H; i += 32) s += xs[i] * w[i];
        #pragma unroll
        for (int o = 16; o > 0; o >>= 1) s += __shfl_xor_sync(0xffffffffu, s, o);
        if (lane == 0) logits[e] = s;
    }
    __syncthreads();
    if (threadIdx.x == 0) {
        int ids[TOPK]; float vals[TOPK];
        unsigned used = 0;
        for (int k = 0; k < TOPK; k++) {
            float best = -INFINITY; int bi = 0;
            for (int e = 0; e < E; e++)
                if (!((used >> e) & 1u) && logits[e] > best) { best = logits[e]; bi = e; }
            used |= (1u << bi); ids[k] = bi; vals[k] = best;
        }
        float mx = vals[0], se = 0.f, w4[TOPK];
        for (int k = 0; k < TOPK; k++) { w4[k] = expf(vals[k] - mx); se += w4[k]; }
        float inv = 1.0f / se;
        for (int k = 0; k < TOPK; k++) {
            int e = ids[k];
            int pos = atomicAdd(&g_count[e], 1);
            g_tok[e * T + pos] = t * TOPK + k;
            g_wt[e * T + pos] = w4[k] * inv;
        }
    }
}

// ------------------------- gate/up fp16 mma GEMM ---------------------------
#define GU_STAGEW 5120
#define GU_STAGEB (GU_STAGEW * 4)
#define GU_SMEMB  (4 * GU_STAGEB)          // 81920 bytes

__global__ void __launch_bounds__(256, 2)
gateup_mma() {
    extern __shared__ uint32_t sm[];
    __shared__ int   styp[E + 1];
    __shared__ int   soff[E];
    __shared__ int   said_s[128];
    __shared__ float swt_s[128];

    int tid = threadIdx.x, lane = tid & 31, wid = tid >> 5;
    int gid = lane >> 2, tig = lane & 3;
    int wm = wid & 3, wn = wid >> 2;

    BLOCK_SCAN(soff, styp);
    int totalW = styp[E] * 8;

    uint32_t sbase = smem_u32(sm);
    int a_ro = lane & 15;
    int a_kw = (lane >> 4) * 16;
    uint32_t adrA0 = sbase + (uint32_t)(wm * 32 + a_ro) * RBYTES + a_kw;
    uint32_t adrA1 = adrA0 + 16 * RBYTES;
    int b_ro = (lane & 7) + ((lane & 16) >> 1);
    int b_kw = (lane & 8) ? 16 : 0;
    uint32_t adrG0 = sbase + 128 * RBYTES + (uint32_t)(wn * 32 + b_ro) * RBYTES + b_kw;
    uint32_t adrG1 = adrG0 + 16 * RBYTES;
    uint32_t adrU0 = adrG0 + 64 * RBYTES;
    uint32_t adrU1 = adrU0 + 16 * RBYTES;

    int ar = tid >> 1, aj = (tid & 1) * 2;
    int gr = tid >> 2, gj = tid & 3;

    for (int w = blockIdx.x; w < totalW; w += gridDim.x) {
        int ytl = w >> 3, xt = w & 7;
        int e = 0;
        while (styp[e + 1] <= ytl) e++;
        int t0 = (ytl - styp[e]) * 128;
        int m0 = xt * 64;
        int n  = g_count[e];
        int gbase = soff[e] + t0;

        __syncthreads();
        if (tid < 128) {
            int slot = t0 + tid;
            bool v = slot < n;
            said_s[tid] = v ? g_tok[e * T + slot] : -1;
            swt_s[tid]  = v ? g_wt[e * T + slot] : 0.f;
        }
        __syncthreads();

        int aid_a = said_s[ar];
        int apred = (aid_a >= 0) ? 16 : 0;
        const char* asrc0 = (const char*)(g_xh + (size_t)((aid_a < 0 ? 0 : aid_a) >> 2) * H) + aj * 16;
        const char* gsrc0 = (const char*)(g_wgh + ((size_t)e * M + m0 + gr) * H) + gj * 16;
        const char* usrc0 = (const char*)(g_wuh + ((size_t)e * M + m0 + gr) * H) + gj * 16;

        float accG[2][4][4], accU[2][4][4];
        #pragma unroll
        for (int i = 0; i < 2; i++)
            #pragma unroll
            for (int j = 0; j < 4; j++)
                #pragma unroll
                for (int q = 0; q < 4; q++) { accG[i][j][q] = 0.f; accU[i][j][q] = 0.f; }

        auto issue = [&](int c, int s) {
            uint32_t st = sbase + (uint32_t)s * GU_STAGEB;
            const char* as = asrc0 + c * 64;
            cp16(st + ar * RBYTES + aj * 16,      as,      apred);
            cp16(st + ar * RBYTES + aj * 16 + 16, as + 16, apred);
            cp16(st + 128 * RBYTES + gr * RBYTES + gj * 16, gsrc0 + c * 64, 16);
            cp16(st + 192 * RBYTES + gr * RBYTES + gj * 16, usrc0 + c * 64, 16);
        };
        auto compute = [&](int s) {
            uint32_t so = (uint32_t)s * GU_STAGEB;
            #pragma unroll
            for (int sub = 0; sub < 2; sub++) {
                uint32_t soo = so + sub * 32;
                uint32_t a0[4], a1[4], g0[4], g1[4], u0[4], u1[4];
                ldm4(a0, adrA0 + soo); ldm4(a1, adrA1 + soo);
                ldm4(g0, adrG0 + soo); ldm4(g1, adrG1 + soo);
                ldm4(u0, adrU0 + soo); ldm4(u1, adrU1 + soo);
                #pragma unroll
                for (int p = 0; p < 2; p++) {
                    const uint32_t* gg = p ? g1 : g0;
                    const uint32_t* uu = p ? u1 : u0;
                    #pragma unroll
                    for (int q = 0; q < 2; q++) {
                        int nt = p * 2 + q;
                        mma_f16(accG[0][nt], a0, gg[q * 2], gg[q * 2 + 1]);
                        mma_f16(accG[1][nt], a1, gg[q * 2], gg[q * 2 + 1]);
                        mma_f16(accU[0][nt], a0, uu[q * 2], uu[q * 2 + 1]);
                        mma_f16(accU[1][nt], a1, uu[q * 2], uu[q * 2 + 1]);
                    }
                }
            }
        };

        const int NC = H / 32;   // 32
        issue(0, 0); CP_COMMIT();
        issue(1, 1); CP_COMMIT();
        issue(2, 2); CP_COMMIT();
        CP_WAIT(2);
        __syncthreads();
        for (int c = 0; c < NC; c++) {
            compute(c & 3);
            if (c + 3 < NC) issue(c + 3, (c + 3) & 3);
            CP_COMMIT();
            CP_WAIT(2);
            __syncthreads();
        }

        // epilogue: h = silu(gate)*up*route_w -> half2 words
        #pragma unroll
        for (int mt = 0; mt < 2; mt++) {
            #pragma unroll
            for (int rh = 0; rh < 2; rh++) {
                int r = wm * 32 + mt * 16 + gid + rh * 8;
                int said = said_s[r];
                if (said < 0) continue;
                float wv = swt_s[r];
                uint32_t* hp = g_hbufw + (size_t)(gbase + r) * (M / 2)
                             + ((m0 + wn * 32) >> 1) + tig;
                #pragma unroll
                for (int nt = 0; nt < 4; nt++) {
                    float g0 = accG[mt][nt][rh * 2 + 0];
                    float g1 = accG[mt][nt][rh * 2 + 1];
                    float u0 = accU[mt][nt][rh * 2 + 0];
                    float u1 = accU[mt][nt][rh * 2 + 1];
                    float o0 = (g0 / (1.f + __expf(-g0))) * u0 * wv;
                    float o1 = (g1 / (1.f + __expf(-g1))) * u1 * wv;
                    hp[nt * 4] = f2h2(o0, o1);
                }
            }
        }
    }
}

// ------------------------- down fp16 mma GEMM ------------------------------
#define DN_STAGEW 5120
#define DN_STAGEB (DN_STAGEW * 4)
#define DN_SMEMB  (4 * DN_STAGEB)          // 81920 bytes

__global__ void __launch_bounds__(256, 2)
down_mma(float* __restrict__ out) {
    extern __shared__ uint32_t sm[];
    __shared__ int styp[E + 1];
    __shared__ int soff[E];
    __shared__ int said_s[128];

    int tid = threadIdx.x, lane = tid & 31, wid = tid >> 5;
    int gid = lane >> 2, tig = lane & 3;
    int wm = wid & 1, wn = wid >> 1;

    BLOCK_SCAN(soff, styp);
    int totalW = styp[E] * 8;

    uint32_t sbase = smem_u32(sm);
    int a_ro = lane & 15;
    int a_kw = (lane >> 4) * 16;
    uint32_t adrA[4];
    #pragma unroll
    for (int mt = 0; mt < 4; mt++)
        adrA[mt] = sbase + (uint32_t)(wm * 64 + mt * 16 + a_ro) * RBYTES + a_kw;
    int b_ro = (lane & 7) + ((lane & 16) >> 1);
    int b_kw = (lane & 8) ? 16 : 0;
    uint32_t adrW0 = sbase + 128 * RBYTES + (uint32_t)(wn * 32 + b_ro) * RBYTES + b_kw;
    uint32_t adrW1 = adrW0 + 16 * RBYTES;

    int ar = tid >> 1, aj = (tid & 1) * 2;

    for (int w = blockIdx.x; w < totalW; w += gridDim.x) {
        int ytl = w >> 3, xt = w & 7;
        int e = 0;
        while (styp[e + 1] <= ytl) e++;
        int t0 = (ytl - styp[e]) * 128;
        int h0 = xt * 128;
        int n  = g_count[e];
        int gbase = soff[e] + t0;

        __syncthreads();
        if (tid < 128) {
            int slot = t0 + tid;
            said_s[tid] = (slot < n) ? g_tok[e * T + slot] : -1;
        }
        __syncthreads();

        const char* asrc0 = (const char*)(g_hbufw + (size_t)(gbase + ar) * (M / 2)) + aj * 16;
        const char* wsrc0 = (const char*)(g_wdh + ((size_t)e * H + h0 + ar) * M) + aj * 16;

        float acc[4][4][4];
        #pragma unroll
        for (int i = 0; i < 4; i++)
            #pragma unroll
            for (int j = 0; j < 4; j++)
                #pragma unroll
                for (int q = 0; q < 4; q++) acc[i][j][q] = 0.f;

        auto issue = [&](int c, int s) {
            uint32_t st = sbase + (uint32_t)s * DN_STAGEB;
            const char* as = asrc0 + c * 64;
            const char* ws = wsrc0 + c * 64;
            cp16(st + ar * RBYTES + aj * 16,      as,      16);
            cp16(st + ar * RBYTES + aj * 16 + 16, as + 16, 16);
            cp16(st + 128 * RBYTES + ar * RBYTES + aj * 16,      ws,      16);
            cp16(st + 128 * RBYTES + ar * RBYTES + aj * 16 + 16, ws + 16, 16);
        };
        auto compute = [&](int s) {
            uint32_t so = (uint32_t)s * DN_STAGEB;
            #pragma unroll
            for (int sub = 0; sub < 2; sub++) {
                uint32_t soo = so + sub * 32;
                uint32_t a[4][4], w0[4], w1[4];
                #pragma unroll
                for (int mt = 0; mt < 4; mt++) ldm4(a[mt], adrA[mt] + soo);
                ldm4(w0, adrW0 + soo); ldm4(w1, adrW1 + soo);
                #pragma unroll
                for (int p = 0; p < 2; p++) {
                    const uint32_t* ww = p ? w1 : w0;
                    #pragma unroll
                    for (int q = 0; q < 2; q++) {
                        int nt = p * 2 + q;
                        #pragma unroll
                        for (int mt = 0; mt < 4; mt++)
                            mma_f16(acc[mt][nt], a[mt], ww[q * 2], ww[q * 2 + 1]);
                    }
                }
            }
        };

        const int NC = M / 32;   // 16
        issue(0, 0); CP_COMMIT();
        issue(1, 1); CP_COMMIT();
        issue(2, 2); CP_COMMIT();
        CP_WAIT(2);
        __syncthreads();
        for (int c = 0; c < NC; c++) {
            compute(c & 3);
            if (c + 3 < NC) issue(c + 3, (c + 3) & 3);
            CP_COMMIT();
            CP_WAIT(2);
            __syncthreads();
        }

        #pragma unroll
        for (int mt = 0; mt < 4; mt++) {
            #pragma unroll
            for (int rh = 0; rh < 2; rh++) {
                int r = wm * 64 + mt * 16 + gid + rh * 8;
                int aid = said_s[r];
                if (aid < 0) continue;
                float* op = out + (size_t)(aid >> 2) * H + h0 + wn * 32 + tig * 2;
                #pragma unroll
                for (int nt = 0; nt < 4; nt++) {
                    atomicAdd(op + nt * 8,     acc[mt][nt][rh * 2 + 0]);
                    atomicAdd(op + nt * 8 + 1, acc[mt][nt][rh * 2 + 1]);
                }
            }
        }
    }
}

// ------------------------- launcher ----------------------------------------
extern "C" void kernel_launch(void* const* d_in, const int* in_sizes, int n_in,
                              void* d_out, int out_size) {
    const float* x      = (const float*)d_in[0];
    const float* gate_w = (const float*)d_in[1];
    const float* w_gate = (const float*)d_in[2];
    const float* w_up   = (const float*)d_in[3];
    const float* w_down = (const float*)d_in[4];
    float* out = (float*)d_out;

    cudaFuncSetAttribute(gateup_mma, cudaFuncAttributeMaxDynamicSharedMemorySize, GU_SMEMB);
    cudaFuncSetAttribute(down_mma,   cudaFuncAttributeMaxDynamicSharedMemorySize, DN_SMEMB);

    cvt_all<<<(NTOT + 255) / 256, 256>>>((const float4*)w_gate, (const float4*)w_up,
                                         (const float4*)w_down, out);
    router_kernel<<<T, 128>>>(x, gate_w);
    gateup_mma<<<296, 256, GU_SMEMB>>>();
    down_mma<<<296, 256, DN_SMEMB>>>(out);
}